// round 17
// baseline (speedup 1.0000x reference)
#include <cuda_runtime.h>
#include <cuda_fp16.h>
#include <cstdint>
#include <cstddef>

typedef __half  mha_h;
typedef __half2 mha_h2;

constexpr int MHA_B  = 4;
constexpr int MHA_S  = 2048;
constexpr int MHA_D  = 1024;
constexpr int MHA_H  = 16;
constexpr int MHA_DK = 64;

// softmax scale folded into Q: exp(q.k/8) == exp2((q*QSCALE).k)
constexpr float MHA_QSCALE = 0.18033688011112042f;   // 0.125 * log2(e)

// ---------------- scratch ----------------
__device__ mha_h g_inh[(size_t)3*8192*1024];                     // input hi
__device__ mha_h g_wh [(size_t)4*1024*1024];                     // weight hi
__device__ mha_h g_Qh[(size_t)8388608];                          // [bh][s][dk] pre-scaled
__device__ mha_h g_Kh[(size_t)8388608];                          // [bh][s][dk]
__device__ mha_h g_Vth[(size_t)8388608];                         // [bh][dk][s]
__device__ mha_h g_Oh[(size_t)8388608];                          // [b][s][d]
__device__ float g_inv[(size_t)64*2048];                         // 1/rowsum

// ---------------- PTX helpers ----------------
__device__ __forceinline__ void mha_cpa16(uint32_t dst, const void* src) {
    asm volatile("cp.async.cg.shared.global [%0], [%1], 16;\n" :: "r"(dst), "l"(src));
}
__device__ __forceinline__ void mha_cp_commit() { asm volatile("cp.async.commit_group;\n"); }
template<int N> __device__ __forceinline__ void mha_cp_wait() {
    asm volatile("cp.async.wait_group %0;\n" :: "n"(N));
}
__device__ __forceinline__ void mha_ldsm4(uint32_t &r0, uint32_t &r1, uint32_t &r2,
                                          uint32_t &r3, uint32_t addr) {
    asm volatile("ldmatrix.sync.aligned.m8n8.x4.shared.b16 {%0,%1,%2,%3}, [%4];\n"
        : "=r"(r0),"=r"(r1),"=r"(r2),"=r"(r3) : "r"(addr));
}
__device__ __forceinline__ void mha_mma(float* d, const uint32_t* a, const uint32_t* b) {
    asm volatile("mma.sync.aligned.m16n8k16.row.col.f32.f16.f16.f32 "
      "{%0,%1,%2,%3}, {%4,%5,%6,%7}, {%8,%9}, {%0,%1,%2,%3};\n"
      : "+f"(d[0]),"+f"(d[1]),"+f"(d[2]),"+f"(d[3])
      : "r"(a[0]),"r"(a[1]),"r"(a[2]),"r"(a[3]),"r"(b[0]),"r"(b[1]));
}
__device__ __forceinline__ uint32_t mha_pack(float a, float b) {
    mha_h2 t = __floats2half2_rn(a, b);
    return *(uint32_t*)&t;
}
__device__ __forceinline__ float mha_ex2(float x) {
    float r;
    asm("ex2.approx.ftz.f32 %0, %1;" : "=f"(r) : "f"(x));
    return r;
}

// ---------------- input/weight split (hi only) ----------------
__global__ void mha_split_in3(const float* __restrict__ q, const float* __restrict__ k,
                              const float* __restrict__ v, mha_h* __restrict__ h) {
    const size_t NIN = (size_t)8192*1024;
    int seg = blockIdx.y;
    const float* x = (seg == 0) ? q : (seg == 1) ? k : v;
    size_t i = (size_t)blockIdx.x*blockDim.x + threadIdx.x;
    if (i >= NIN/4) return;
    float4 val = ((const float4*)x)[i];
    size_t o = (size_t)seg*(NIN/2) + 2*i;
    ((mha_h2*)h)[o]   = __floats2half2_rn(val.x, val.y);
    ((mha_h2*)h)[o+1] = __floats2half2_rn(val.z, val.w);
}
__global__ void mha_split_w4h(const float* __restrict__ wq, const float* __restrict__ wk,
                              const float* __restrict__ wv, const float* __restrict__ wo,
                              mha_h* __restrict__ h) {
    const size_t NW = (size_t)1024*1024;
    int seg = blockIdx.y;
    const float* x = (seg == 0) ? wq : (seg == 1) ? wk : (seg == 2) ? wv : wo;
    size_t i = (size_t)blockIdx.x*blockDim.x + threadIdx.x;
    if (i >= NW/4) return;
    float4 val = ((const float4*)x)[i];
    size_t o = (size_t)seg*(NW/2) + 2*i;
    ((mha_h2*)h)[o]   = __floats2half2_rn(val.x, val.y);
    ((mha_h2*)h)[o+1] = __floats2half2_rn(val.z, val.w);
}

// ---------------- projection GEMM core (3-stage pipeline) ----------------
__device__ __forceinline__ uint32_t mha_swz(int row, int kc) {
    return (uint32_t)(row*64 + ((kc ^ ((row >> 1) & 3)) << 4));
}

__device__ __forceinline__ void mha_issue(
    uint32_t s0, int tid, int bm, int bn, int kk,
    const mha_h* pAh, const mha_h* pBh)
{
    constexpr int K = 1024;
    constexpr int ABYTES = 128 * 64;
    #pragma unroll
    for (int c = tid; c < 512; c += 256) {
        int row = c >> 2, kc = c & 3;
        uint32_t off = mha_swz(row, kc);
        size_t g = (size_t)(bm + row) * K + kk + kc*8;
        mha_cpa16(s0 + off, pAh + g);
    }
    #pragma unroll
    for (int c = tid; c < 512; c += 256) {
        int row = c >> 2, kc = c & 3;
        uint32_t off = mha_swz(row, kc);
        size_t g = (size_t)(bn + row) * K + kk + kc*8;
        mha_cpa16(s0 + ABYTES + off, pBh + g);
    }
}

__device__ __forceinline__ void mha_gemm_core(
    uint32_t sbase, int tid, int warp, int lane, int bm, int bn,
    const mha_h* Ah, const mha_h* Bh, float acc[4][4][4])
{
    constexpr int ABYTES = 128 * 64;
    constexpr int STAGE  = 2 * ABYTES;      // 32KB per stage
    int wm = warp >> 2, wn = warp & 3;

    #pragma unroll
    for (int i = 0; i < 4; i++)
        #pragma unroll
        for (int j = 0; j < 4; j++)
            #pragma unroll
            for (int r = 0; r < 4; r++) acc[i][j][r] = 0.f;

    // 3-stage: two tiles in flight
    mha_issue(sbase,          tid, bm, bn, 0,  Ah, Bh);
    mha_cp_commit();
    mha_issue(sbase + STAGE,  tid, bm, bn, 32, Ah, Bh);
    mha_cp_commit();

    for (int it = 0; it < 32; it++) {
        mha_cp_wait<1>(); __syncthreads();
        if (it + 2 < 32)
            mha_issue(sbase + ((it+2)%3)*STAGE, tid, bm, bn, (it+2)*32, Ah, Bh);
        mha_cp_commit();

        uint32_t sAh0 = sbase + (it%3)*STAGE;
        uint32_t sBh0 = sAh0 + ABYTES;

        #pragma unroll
        for (int ks = 0; ks < 2; ks++) {
            int kc0 = ks * 2;
            uint32_t fah[4][4], fbh[4][2];
            #pragma unroll
            for (int mt = 0; mt < 4; mt++) {
                int r  = wm*64 + mt*16 + (lane & 15);
                int kc = kc0 + (lane >> 4);
                mha_ldsm4(fah[mt][0],fah[mt][1],fah[mt][2],fah[mt][3],
                          sAh0 + mha_swz(r, kc));
            }
            #pragma unroll
            for (int g = 0; g < 2; g++) {
                int r  = wn*32 + g*16 + (lane & 15);
                int kc = kc0 + (lane >> 4);
                uint32_t t0,t1,t2,t3;
                mha_ldsm4(t0,t1,t2,t3, sBh0 + mha_swz(r, kc));
                fbh[2*g][0]=t0; fbh[2*g][1]=t2; fbh[2*g+1][0]=t1; fbh[2*g+1][1]=t3;
            }
            #pragma unroll
            for (int mt = 0; mt < 4; mt++)
                #pragma unroll
                for (int nt = 0; nt < 4; nt++)
                    mha_mma(acc[mt][nt], fah[mt], fbh[nt]);
        }
        __syncthreads();
    }
}

// merged Q/K/V projection; Q epilogue pre-scales by MHA_QSCALE
__global__ void __launch_bounds__(256, 2) mha_gemm_qkv(
    const mha_h* __restrict__ inh, const mha_h* __restrict__ wh,
    const float* __restrict__ bq, const float* __restrict__ bk,
    const float* __restrict__ bv,
    mha_h* __restrict__ Qh, mha_h* __restrict__ Kh, mha_h* __restrict__ Vth)
{
    extern __shared__ char smem[];
    uint32_t sbase = (uint32_t)__cvta_generic_to_shared(smem);
    int tid = threadIdx.x, warp = tid >> 5, lane = tid & 31;
    int bm = blockIdx.y * 128, bn = blockIdx.x * 128;
    int z = blockIdx.z;

    const size_t NIN = (size_t)8192*1024;
    const size_t NW  = (size_t)1024*1024;
    const mha_h* Ah = inh + (size_t)z*NIN;
    const mha_h* Bh = wh  + (size_t)z*NW;
    const float* bias = (z == 0) ? bq : (z == 1) ? bk : bv;
    mha_h* Ch = (z == 0) ? Qh : (z == 1) ? Kh : Vth;
    float oscale = (z == 0) ? MHA_QSCALE : 1.f;

    float acc[4][4][4];
    mha_gemm_core(sbase, tid, warp, lane, bm, bn, Ah, Bh, acc);

    int wm = warp >> 2, wn = warp & 3;
    #pragma unroll
    for (int mt = 0; mt < 4; mt++)
        #pragma unroll
        for (int nt = 0; nt < 4; nt++) {
            int r0 = bm + wm*64 + mt*16 + (lane >> 2);
            int c0 = bn + wn*32 + nt*8  + (lane & 3)*2;
            #pragma unroll
            for (int half = 0; half < 2; half++) {
                int r = r0 + half*8;
                float v0 = (acc[mt][nt][2*half]   + bias[c0])   * oscale;
                float v1 = (acc[mt][nt][2*half+1] + bias[c0+1]) * oscale;
                int b = r >> 11, s = r & (MHA_S-1);
                int h = c0 >> 6, dk = c0 & 63;
                if (z < 2) {
                    size_t idx = (((size_t)(b*MHA_H + h))*MHA_S + s)*MHA_DK + dk;
                    *(mha_h2*)(Ch + idx) = __floats2half2_rn(v0, v1);
                } else {
                    size_t idx = (((size_t)(b*MHA_H + h))*MHA_DK + dk)*MHA_S + s;
                    Ch[idx]         = __float2half_rn(v0);
                    Ch[idx + MHA_S] = __float2half_rn(v1);
                }
            }
        }
}

// output projection: fp32 + bias
__global__ void __launch_bounds__(256, 2) mha_gemm_out(
    const mha_h* __restrict__ Ah, const mha_h* __restrict__ Bh,
    const float* __restrict__ bias, float* __restrict__ Cf)
{
    extern __shared__ char smem[];
    uint32_t sbase = (uint32_t)__cvta_generic_to_shared(smem);
    int tid = threadIdx.x, warp = tid >> 5, lane = tid & 31;
    int bm = blockIdx.y * 128, bn = blockIdx.x * 128;

    float acc[4][4][4];
    mha_gemm_core(sbase, tid, warp, lane, bm, bn, Ah, Bh, acc);

    int wm = warp >> 2, wn = warp & 3;
    #pragma unroll
    for (int mt = 0; mt < 4; mt++)
        #pragma unroll
        for (int nt = 0; nt < 4; nt++) {
            int r0 = bm + wm*64 + mt*16 + (lane >> 2);
            int c0 = bn + wn*32 + nt*8  + (lane & 3)*2;
            #pragma unroll
            for (int half = 0; half < 2; half++) {
                int r = r0 + half*8;
                float2 o = make_float2(acc[mt][nt][2*half]   + bias[c0],
                                       acc[mt][nt][2*half+1] + bias[c0+1]);
                *(float2*)(Cf + (size_t)r*MHA_D + c0) = o;
            }
        }
}

// =================== flash attention, two kernels ============================
constexpr int FS_KB  = 128*128;
constexpr int FS_VB  = 64*256;
constexpr int FS1_SMEM = 2*FS_KB;             // p1: 32KB, 2 CTAs/SM
constexpr int FS2_STAGE = FS_KB + FS_VB;      // 32KB
constexpr int FS2_SMEM  = 2*FS2_STAGE;        // 64KB -> 2 CTAs/SM

__device__ __forceinline__ uint32_t fs_swzk(int row, int c) {
    return (uint32_t)(row*128 + ((c ^ (row & 7)) << 4));
}
__device__ __forceinline__ uint32_t fs_swzv(int row, int c) {
    return (uint32_t)(row*256 + ((c ^ (row & 7)) << 4));
}

__device__ __forceinline__ void fs_loadK(uint32_t sb, int tid, int bh, int t,
                                         const mha_h* Kh) {
    #pragma unroll
    for (int i = tid; i < 1024; i += 256) {
        int row = i >> 3, c = i & 7;
        size_t g = ((size_t)bh*MHA_S + t*128 + row)*MHA_DK + c*8;
        mha_cpa16(sb + fs_swzk(row, c), Kh + g);
    }
}
__device__ __forceinline__ void fs_loadV(uint32_t sb, int tid, int bh, int t,
                                         const mha_h* Vh) {
    #pragma unroll
    for (int i = tid; i < 1024; i += 256) {
        int row = i >> 4, c = i & 15;
        size_t g = ((size_t)bh*MHA_DK + row)*MHA_S + t*128 + c*8;
        mha_cpa16(sb + FS_KB + fs_swzv(row, c), Vh + g);
    }
}

// Q A-fragments loaded directly from gmem for one 16-row tile at rowbase
__device__ __forceinline__ void fs_loadQfrag(
    uint32_t qfh[4][4], const mha_h* Qh, int bh, int rowbase, int lane)
{
    int row = rowbase + (lane >> 2);
    const mha_h* base = Qh + ((size_t)bh*MHA_S + row)*MHA_DK + (lane & 3)*2;
    #pragma unroll
    for (int j = 0; j < 4; j++) {
        qfh[j][0] = *(const uint32_t*)(base + j*16);
        qfh[j][1] = *(const uint32_t*)(base + j*16 + 8*MHA_DK);
        qfh[j][2] = *(const uint32_t*)(base + j*16 + 8);
        qfh[j][3] = *(const uint32_t*)(base + j*16 + 8*MHA_DK + 8);
    }
}

// 16x64 score half-tile (Q pre-scaled; result feeds ex2 directly)
__device__ __forceinline__ void fs_scores_hi(
    float acc[8][4], uint32_t kbase, int hf, int lane, const uint32_t qh[4][4])
{
    #pragma unroll
    for (int nt = 0; nt < 8; nt++)
        #pragma unroll
        for (int r = 0; r < 4; r++) acc[nt][r] = 0.f;
    #pragma unroll
    for (int j = 0; j < 4; j++) {
        uint32_t kh[8][2];
        #pragma unroll
        for (int g = 0; g < 4; g++) {
            int r = hf*64 + g*16 + (lane & 15);
            int c = 2*j + (lane >> 4);
            uint32_t t0,t1,t2,t3;
            mha_ldsm4(t0,t1,t2,t3, kbase + fs_swzk(r, c));
            kh[2*g][0]=t0; kh[2*g][1]=t2; kh[2*g+1][0]=t1; kh[2*g+1][1]=t3;
        }
        #pragma unroll
        for (int nt = 0; nt < 8; nt++)
            mha_mma(acc[nt], qh[j], kh[nt]);
    }
}

// pass 1: MT=2 (CTA = 256 q rows, warp = 32 rows) -> g_inv
__global__ void __launch_bounds__(256, 2) mha_flash_p1(
    const mha_h* __restrict__ Qh, const mha_h* __restrict__ Kh,
    float* __restrict__ ginv)
{
    extern __shared__ char smem[];
    uint32_t stg = (uint32_t)__cvta_generic_to_shared(smem);

    int tid = threadIdx.x;
    int warp = tid >> 5, lane = tid & 31;
    int bh = blockIdx.y;
    int q0 = blockIdx.x * 256;

    uint32_t qfh[2][4][4];
    fs_loadQfrag(qfh[0], Qh, bh, q0 + warp*32,      lane);
    fs_loadQfrag(qfh[1], Qh, bh, q0 + warp*32 + 16, lane);
    float s[2][2] = {{0.f,0.f},{0.f,0.f}};

    fs_loadK(stg, tid, bh, 0, Kh);
    mha_cp_commit();

    for (int t = 0; t < 16; t++) {
        if (t + 1 < 16) fs_loadK(stg + ((t+1)&1)*FS_KB, tid, bh, t+1, Kh);
        mha_cp_commit();
        mha_cp_wait<1>(); __syncthreads();

        uint32_t kb = stg + (t&1)*FS_KB;
        #pragma unroll
        for (int hf = 0; hf < 2; hf++) {
            float acc[2][8][4];
            #pragma unroll
            for (int mt = 0; mt < 2; mt++)
                #pragma unroll
                for (int nt = 0; nt < 8; nt++)
                    #pragma unroll
                    for (int r = 0; r < 4; r++) acc[mt][nt][r] = 0.f;
            #pragma unroll
            for (int j = 0; j < 4; j++) {
                uint32_t kh[8][2];
                #pragma unroll
                for (int g = 0; g < 4; g++) {
                    int r = hf*64 + g*16 + (lane & 15);
                    int c = 2*j + (lane >> 4);
                    uint32_t t0,t1,t2,t3;
                    mha_ldsm4(t0,t1,t2,t3, kb + fs_swzk(r, c));
                    kh[2*g][0]=t0; kh[2*g][1]=t2; kh[2*g+1][0]=t1; kh[2*g+1][1]=t3;
                }
                #pragma unroll
                for (int mt = 0; mt < 2; mt++)
                    #pragma unroll
                    for (int nt = 0; nt < 8; nt++)
                        mha_mma(acc[mt][nt], qfh[mt][j], kh[nt]);
            }
            #pragma unroll
            for (int mt = 0; mt < 2; mt++)
                #pragma unroll
                for (int nt = 0; nt < 8; nt++) {
                    s[mt][0] += mha_ex2(acc[mt][nt][0]) + mha_ex2(acc[mt][nt][1]);
                    s[mt][1] += mha_ex2(acc[mt][nt][2]) + mha_ex2(acc[mt][nt][3]);
                }
        }
        __syncthreads();
    }

    #pragma unroll
    for (int mt = 0; mt < 2; mt++) {
        float a = s[mt][0], b = s[mt][1];
        a += __shfl_xor_sync(0xffffffffu, a, 1);
        a += __shfl_xor_sync(0xffffffffu, a, 2);
        b += __shfl_xor_sync(0xffffffffu, b, 1);
        b += __shfl_xor_sync(0xffffffffu, b, 2);
        if ((lane & 3) == 0) {
            int row = q0 + warp*32 + mt*16 + (lane >> 2);
            ginv[(size_t)bh*MHA_S + row]     = 1.f / a;
            ginv[(size_t)bh*MHA_S + row + 8] = 1.f / b;
        }
    }
}

// pass 2: P = exp2(S')*inv, write P, O += P·Vh (2 CTAs/SM) — unchanged
__global__ void __launch_bounds__(256, 2) mha_flash_p2(
    const mha_h* __restrict__ Qh, const mha_h* __restrict__ Kh,
    const mha_h* __restrict__ Vh, const float* __restrict__ ginv,
    float* __restrict__ attn, mha_h* __restrict__ Oh)
{
    extern __shared__ char smem[];
    uint32_t stg = (uint32_t)__cvta_generic_to_shared(smem);

    int tid = threadIdx.x;
    int warp = tid >> 5, lane = tid & 31;
    int bh = blockIdx.y;
    int q0 = blockIdx.x * 128;

    uint32_t qfh[4][4];
    fs_loadQfrag(qfh, Qh, bh, q0 + warp*16, lane);

    int qrow0 = q0 + warp*16 + (lane >> 2);
    float inv0 = ginv[(size_t)bh*MHA_S + qrow0];
    float inv1 = ginv[(size_t)bh*MHA_S + qrow0 + 8];

    float oacc[8][4];
    #pragma unroll
    for (int nd = 0; nd < 8; nd++)
        #pragma unroll
        for (int r = 0; r < 4; r++) oacc[nd][r] = 0.f;

    fs_loadK(stg, tid, bh, 0, Kh);
    fs_loadV(stg, tid, bh, 0, Vh);
    mha_cp_commit();

    for (int t = 0; t < 16; t++) {
        if (t + 1 < 16) {
            fs_loadK(stg + ((t+1)&1)*FS2_STAGE, tid, bh, t+1, Kh);
            fs_loadV(stg + ((t+1)&1)*FS2_STAGE, tid, bh, t+1, Vh);
        }
        mha_cp_commit();
        mha_cp_wait<1>(); __syncthreads();

        uint32_t kb = stg + (t&1)*FS2_STAGE;
        #pragma unroll
        for (int hf = 0; hf < 2; hf++) {
            float acc[8][4];
            fs_scores_hi(acc, kb, hf, lane, qfh);
            #pragma unroll
            for (int nt = 0; nt < 8; nt++) {
                acc[nt][0] = mha_ex2(acc[nt][0])*inv0;
                acc[nt][1] = mha_ex2(acc[nt][1])*inv0;
                acc[nt][2] = mha_ex2(acc[nt][2])*inv1;
                acc[nt][3] = mha_ex2(acc[nt][3])*inv1;
            }
            {
                size_t rb0 = ((size_t)bh*MHA_S + qrow0)    *MHA_S + t*128 + hf*64 + (lane&3)*2;
                size_t rb1 = ((size_t)bh*MHA_S + qrow0 + 8)*MHA_S + t*128 + hf*64 + (lane&3)*2;
                #pragma unroll
                for (int nt = 0; nt < 8; nt++) {
                    *(float2*)(attn + rb0 + nt*8) = make_float2(acc[nt][0], acc[nt][1]);
                    *(float2*)(attn + rb1 + nt*8) = make_float2(acc[nt][2], acc[nt][3]);
                }
            }
            #pragma unroll
            for (int kk = 0; kk < 4; kk++) {
                uint32_t pah[4];
                pah[0] = mha_pack(acc[2*kk][0],   acc[2*kk][1]);
                pah[1] = mha_pack(acc[2*kk][2],   acc[2*kk][3]);
                pah[2] = mha_pack(acc[2*kk+1][0], acc[2*kk+1][1]);
                pah[3] = mha_pack(acc[2*kk+1][2], acc[2*kk+1][3]);

                uint32_t vbh[8][2];
                #pragma unroll
                for (int g = 0; g < 4; g++) {
                    int r = g*16 + (lane & 15);
                    int c = 2*(hf*4 + kk) + (lane >> 4);
                    uint32_t t0,t1,t2,t3;
                    mha_ldsm4(t0,t1,t2,t3, kb + FS_KB + fs_swzv(r, c));
                    vbh[2*g][0]=t0; vbh[2*g][1]=t2; vbh[2*g+1][0]=t1; vbh[2*g+1][1]=t3;
                }
                #pragma unroll
                for (int nd = 0; nd < 8; nd++)
                    mha_mma(oacc[nd], pah, vbh[nd]);
            }
        }
        __syncthreads();
    }

    int b = bh >> 4, h = bh & 15;
    #pragma unroll
    for (int nd = 0; nd < 8; nd++) {
        int dk = nd*8 + (lane & 3)*2;
        size_t i0 = ((size_t)(b*MHA_S + qrow0))    *MHA_D + h*MHA_DK + dk;
        size_t i1 = ((size_t)(b*MHA_S + qrow0 + 8))*MHA_D + h*MHA_DK + dk;
        *(mha_h2*)(Oh + i0) = __floats2half2_rn(oacc[nd][0], oacc[nd][1]);
        *(mha_h2*)(Oh + i1) = __floats2half2_rn(oacc[nd][2], oacc[nd][3]);
    }
}

// ---------------- host ----------------
extern "C" void kernel_launch(void* const* d_in, const int* in_sizes, int n_in,
                              void* d_out, int out_size)
{
    (void)in_sizes; (void)n_in; (void)out_size;
    const float* q  = (const float*)d_in[0];
    const float* k  = (const float*)d_in[1];
    const float* v  = (const float*)d_in[2];
    const float* wq = (const float*)d_in[3];
    const float* bq = (const float*)d_in[4];
    const float* wk = (const float*)d_in[5];
    const float* bk = (const float*)d_in[6];
    const float* wv = (const float*)d_in[7];
    const float* bv = (const float*)d_in[8];
    const float* wo = (const float*)d_in[9];
    const float* bo = (const float*)d_in[10];

    float* out  = (float*)d_out;
    float* attn = out + (size_t)MHA_B * MHA_S * MHA_D;

    mha_h *inh, *wh, *Qh, *Kh, *Vth, *Oh;
    float *ginv;
    cudaGetSymbolAddress((void**)&inh,  g_inh);
    cudaGetSymbolAddress((void**)&wh,   g_wh);
    cudaGetSymbolAddress((void**)&Qh,   g_Qh);
    cudaGetSymbolAddress((void**)&Kh,   g_Kh);
    cudaGetSymbolAddress((void**)&Vth,  g_Vth);
    cudaGetSymbolAddress((void**)&Oh,   g_Oh);
    cudaGetSymbolAddress((void**)&ginv, g_inv);

    const size_t NIN = (size_t)8192*1024;
    const size_t NW  = (size_t)1024*1024;

    mha_split_in3<<<dim3((unsigned)(NIN/4/256), 3), 256>>>(q, k, v, inh);
    mha_split_w4h<<<dim3((unsigned)(NW/4/256),  4), 256>>>(wq, wk, wv, wo, wh);

    const int SMG = 3 * (128*64 + 128*64);   // 3 stages = 98304 B
    cudaFuncSetAttribute(mha_gemm_qkv, cudaFuncAttributeMaxDynamicSharedMemorySize, SMG);
    cudaFuncSetAttribute(mha_gemm_out, cudaFuncAttributeMaxDynamicSharedMemorySize, SMG);
    cudaFuncSetAttribute(mha_flash_p1, cudaFuncAttributeMaxDynamicSharedMemorySize, FS1_SMEM);
    cudaFuncSetAttribute(mha_flash_p2, cudaFuncAttributeMaxDynamicSharedMemorySize, FS2_SMEM);

    dim3 t(256);

    mha_gemm_qkv<<<dim3(8, 64, 3), t, SMG>>>(inh, wh, bq, bk, bv, Qh, Kh, Vth);

    mha_flash_p1<<<dim3(8,  MHA_B*MHA_H), t, FS1_SMEM>>>(Qh, Kh, ginv);
    mha_flash_p2<<<dim3(16, MHA_B*MHA_H), t, FS2_SMEM>>>(Qh, Kh, Vth, ginv, attn, Oh);

    mha_gemm_out<<<dim3(8, 64), t, SMG>>>(Oh, wh + 3*NW, bo, out);
}